// round 5
// baseline (speedup 1.0000x reference)
#include <cuda_runtime.h>
#include <cuda_fp16.h>

#define NP 100000
#define KN 16
#define NK (NP*KN)

// ---------------- device scratch ----------------
__device__ int      g_cnt[NP];
__device__ float    g_g1[NP*64];          // f-path layer1 pre-BN (fp32)
__device__ float    g_g2[NP*64];          // f-path layer2 pre-BN (fp32)
__device__ unsigned g_fh[NP*32];          // feats as half2 words, K-permuted
__device__ unsigned g_g1h[NP*32];         // relu(BN1(g1)) as half2 words, K-permuted
__device__ __half   g_fph[NP*64];         // fpost = relu(BN2(g2)) fp16, linear layout
__device__ unsigned g_w1h[64*32];         // fw1 half2, K-permuted
__device__ unsigned g_w2h[64*32];         // fw2 half2, K-permuted
__device__ float    g_y1w[NK*8];
__device__ float    g_y2w[NK*8];
__device__ unsigned g_newh[NP*512];       // new_flat as half2 words, K-permuted
__device__ unsigned g_lwth[64*512];       // lin_w as half2 words, K-permuted
__device__ float    g_z[NP*64];
__device__ float    g_stats[448];
__device__ float    g_ss[448];

#define F1_OFF 0
#define W1_OFF 128
#define F2_OFF 144
#define W2_OFF 272
#define W3_OFF 288
#define Z_OFF  320

#define EPS_BN 1e-5f

// ---------------- init ----------------
__global__ void k_zero() {
    int i = blockIdx.x * 256 + threadIdx.x;
    if (i < NP)  g_cnt[i] = 0;
    if (i < 448) g_stats[i] = 0.f;
}

__global__ void k_cnt(const int* __restrict__ knn) {
    int i = blockIdx.x * 256 + threadIdx.x;
    if (i < NK) atomicAdd(&g_cnt[knn[i]], 1);
}

// ---------------- stats helper ----------------
template<int CH>
__device__ __forceinline__ void stats_reduce(float* ls, float* lss, int off) {
    const unsigned FULL = 0xffffffffu;
    #pragma unroll
    for (int c = 0; c < CH; c++) {
        #pragma unroll
        for (int o = 16; o; o >>= 1) {
            ls[c]  += __shfl_down_sync(FULL, ls[c],  o);
            lss[c] += __shfl_down_sync(FULL, lss[c], o);
        }
    }
    __shared__ float sred[2 * 8 * CH];
    int wid = threadIdx.x >> 5, lane = threadIdx.x & 31;
    if (lane == 0) {
        #pragma unroll
        for (int c = 0; c < CH; c++) {
            sred[wid * CH + c]          = ls[c];
            sred[8 * CH + wid * CH + c] = lss[c];
        }
    }
    __syncthreads();
    if (threadIdx.x < CH) {
        float a = 0.f, b = 0.f;
        #pragma unroll
        for (int w = 0; w < 8; w++) {
            a += sred[w * CH + threadIdx.x];
            b += sred[8 * CH + w * CH + threadIdx.x];
        }
        atomicAdd(&g_stats[off + threadIdx.x], a);
        atomicAdd(&g_stats[off + CH + threadIdx.x], b);
    }
}

// ---------------- fp16 helpers ----------------
__device__ __forceinline__ unsigned packh2(float a, float b) {
    __half2 h = __floats2half2_rn(a, b);
    return *(unsigned*)&h;
}

__device__ __forceinline__ void mma_f16(float* c, unsigned a0, unsigned a1,
                                        unsigned a2, unsigned a3,
                                        unsigned b0, unsigned b1) {
    asm volatile("mma.sync.aligned.m16n8k16.row.col.f32.f16.f16.f32 "
                 "{%0,%1,%2,%3}, {%4,%5,%6,%7}, {%8,%9}, {%0,%1,%2,%3};"
                 : "+f"(c[0]), "+f"(c[1]), "+f"(c[2]), "+f"(c[3])
                 : "r"(a0), "r"(a1), "r"(a2), "r"(a3), "r"(b0), "r"(b1));
}

__device__ __forceinline__ void cp16(void* sptr, const void* gptr) {
    unsigned saddr = (unsigned)__cvta_generic_to_shared(sptr);
    asm volatile("cp.async.cg.shared.global [%0], [%1], 16;" :: "r"(saddr), "l"(gptr));
}

__device__ __forceinline__ int wperm(int j) {   // word pos within 8-word k-group
    return ((j & 3) << 1) | (j >> 2);
}

// ---------------- preps: fp32 -> half2 words, K-permuted ----------------
// rows of 64 floats -> 32 words, each 8-word group permuted.
__global__ void k_prepf(const float* __restrict__ src) {   // feats -> g_fh
    int i = blockIdx.x * 256 + threadIdx.x;
    if (i < NP * 32) {
        int row = i >> 5, W = i & 31;
        unsigned v = packh2(src[row * 64 + 2 * W], src[row * 64 + 2 * W + 1]);
        g_fh[row * 32 + (W & ~7) + wperm(W & 7)] = v;
    }
}

__global__ void k_prepw(const float* __restrict__ w1, const float* __restrict__ w2) {
    int i = blockIdx.x * 256 + threadIdx.x;   // over 2*64*32
    if (i < 2 * 64 * 32) {
        const float* src = (i < 64 * 32) ? w1 : w2;
        unsigned* dst = (i < 64 * 32) ? g_w1h : g_w2h;
        int r = i & (64 * 32 - 1);
        int row = r >> 5, W = r & 31;
        unsigned v = packh2(src[row * 64 + 2 * W], src[row * 64 + 2 * W + 1]);
        dst[row * 32 + (W & ~7) + wperm(W & 7)] = v;
    }
}

__global__ void k_preph(const float* __restrict__ lw) {   // lin_w -> g_lwth
    int i = blockIdx.x * 256 + threadIdx.x;   // over 64*512 words
    if (i < 64 * 512) {
        int row = i >> 9, W = i & 511;
        unsigned v = packh2(lw[row * 1024 + 2 * W], lw[row * 1024 + 2 * W + 1]);
        g_lwth[row * 512 + (W & ~7) + wperm(W & 7)] = v;
    }
}

// ---------------- mid: g1h = half(relu(BN1(g_g1))), K-permuted ----------------
__global__ void k_mid() {
    int i = blockIdx.x * 256 + threadIdx.x;
    if (i < NP * 32) {
        int row = i >> 5, W = i & 31;
        int c = 2 * W;
        float y0 = g_g1[row * 64 + c], y1 = g_g1[row * 64 + c + 1];
        y0 = fmaxf(g_ss[F1_OFF + c] * y0 + g_ss[F1_OFF + 64 + c], 0.f);
        y1 = fmaxf(g_ss[F1_OFF + c + 1] * y1 + g_ss[F1_OFF + 64 + c + 1], 0.f);
        g_g1h[row * 32 + (W & ~7) + wperm(W & 7)] = packh2(y0, y1);
    }
}

// ---------------- f-path conv via fp16 mma: dst = inH(NPx64) @ wH^T(64x64) ----------------
// 128 points x 64 out per block; K = 64 halves = 32 words; count-weighted stats.
#define FP 36
#define FA (128*FP)
#define FB (64*FP)

__global__ __launch_bounds__(256) void k_fmma(const unsigned* __restrict__ inH,
                                              const unsigned* __restrict__ wH,
                                              const float* __restrict__ B,
                                              float* __restrict__ dst,
                                              int statoff) {
    __shared__ unsigned As[FA];
    __shared__ unsigned Bs[FB];
    __shared__ float sred[128];
    int t = threadIdx.x;
    int rbase = blockIdx.x * 128;
    int lane = t & 31, grp = lane >> 2, qid = lane & 3;
    int m0 = (t >> 5) * 16;

    if (rbase + 128 > NP) {
        for (int i = t; i < FA; i += 256) As[i] = 0u;
        __syncthreads();
    }
    if (t < 128) sred[t] = 0.f;

    // load A: 128 rows x 32 words (4 cp16/thread)
    #pragma unroll
    for (int r4 = 0; r4 < 4; r4++) {
        int seg = t + r4 * 256;
        int row = seg >> 3, w16 = seg & 7;
        if (rbase + row < NP)
            cp16(As + row * FP + w16 * 4, inH + (size_t)(rbase + row) * 32 + w16 * 4);
    }
    // load B: 64 rows x 32 words (2 cp16/thread)
    #pragma unroll
    for (int r2 = 0; r2 < 2; r2++) {
        int seg = t + r2 * 256;
        int row = seg >> 3, w16 = seg & 7;
        cp16(Bs + row * FP + w16 * 4, wH + row * 32 + w16 * 4);
    }
    asm volatile("cp.async.commit_group;");
    asm volatile("cp.async.wait_group 0;");
    __syncthreads();

    float cf[8][4];
    #pragma unroll
    for (int nt = 0; nt < 8; nt++)
        #pragma unroll
        for (int j = 0; j < 4; j++) cf[nt][j] = 0.f;

    #pragma unroll
    for (int ks = 0; ks < 4; ks++) {
        uint2 aLo = *(uint2*)&As[(m0 + grp) * FP + ks * 8 + qid * 2];
        uint2 aHi = *(uint2*)&As[(m0 + grp + 8) * FP + ks * 8 + qid * 2];
        #pragma unroll
        for (int nt = 0; nt < 8; nt++) {
            uint2 b = *(uint2*)&Bs[(nt * 8 + grp) * FP + ks * 8 + qid * 2];
            mma_f16(cf[nt], aLo.x, aHi.x, aLo.y, aHi.y, b.x, b.y);
        }
    }

    int r0 = rbase + m0 + grp, r1 = r0 + 8;
    float w0 = (r0 < NP) ? (float)g_cnt[r0] : 0.f;
    float w1v = (r1 < NP) ? (float)g_cnt[r1] : 0.f;
    #pragma unroll
    for (int nt = 0; nt < 8; nt++) {
        int c0 = nt * 8 + 2 * qid;
        float b0v = __ldg(&B[c0]), b1v = __ldg(&B[c0 + 1]);
        float z0 = cf[nt][0] + b0v, z1 = cf[nt][1] + b1v;
        float z2 = cf[nt][2] + b0v, z3 = cf[nt][3] + b1v;
        if (r0 < NP) *(float2*)&dst[(size_t)r0 * 64 + c0] = make_float2(z0, z1);
        if (r1 < NP) *(float2*)&dst[(size_t)r1 * 64 + c0] = make_float2(z2, z3);
        atomicAdd(&sred[c0],     w0 * z0 + w1v * z2);
        atomicAdd(&sred[c0 + 1], w0 * z1 + w1v * z3);
        atomicAdd(&sred[64 + c0],     w0 * z0 * z0 + w1v * z2 * z2);
        atomicAdd(&sred[64 + c0 + 1], w0 * z1 * z1 + w1v * z3 * z3);
    }
    __syncthreads();
    if (t < 128) atomicAdd(&g_stats[statoff + t], sred[t]);
}

// ---------------- w-path layer 1 ----------------
__global__ __launch_bounds__(256, 3) void k_w1(const float* __restrict__ xyz,
                                               const float* __restrict__ cov,
                                               const float* __restrict__ feats,
                                               const int* __restrict__ knn,
                                               const float* __restrict__ ww1,
                                               const float* __restrict__ wb1) {
    __shared__ float wsm[112];
    __shared__ float bsm[8];
    int t = threadIdx.x;
    if (t < 112) wsm[t] = ww1[t];
    if (t < 8)   bsm[t] = wb1[t];
    __syncthreads();
    float ls[8], lss[8];
    #pragma unroll
    for (int o = 0; o < 8; o++) { ls[o] = 0.f; lss[o] = 0.f; }
    for (int i = blockIdx.x * 256 + t; i < NK; i += gridDim.x * 256) {
        int n = i >> 4;
        int j  = knn[i];
        int j0 = knn[n << 4];
        float lx = xyz[j * 3 + 0] - xyz[j0 * 3 + 0];
        float ly = xyz[j * 3 + 1] - xyz[j0 * 3 + 1];
        float lz = xyz[j * 3 + 2] - xyz[j0 * 3 + 2];
        float nax = feats[j * 64 + 3],  nay = feats[j * 64 + 4],  naz = feats[j * 64 + 5];
        float nmx = feats[j0 * 64 + 3], nmy = feats[j0 * 64 + 4], nmz = feats[j0 * 64 + 5];
        float rn = sqrtf(lx * lx + ly * ly + lz * lz);
        float inv = 1.f / fmaxf(rn, 1e-12f);
        float rx = lx * inv, ry = ly * inv, rz = lz * inv;
        float dot = nmx * rx + nmy * ry + nmz * rz;
        float vx = nmx - dot * rx, vy = nmy - dot * ry, vz = nmz - dot * rz;
        float vi = 1.f / fmaxf(sqrtf(vx * vx + vy * vy + vz * vz), 1e-12f);
        vx *= vi; vy *= vi; vz *= vi;
        float wx = ry * vz - rz * vy;
        float wy = rz * vx - rx * vz;
        float wz = rx * vy - ry * vx;
        float wi = 1.f / fmaxf(sqrtf(wx * wx + wy * wy + wz * wz), 1e-12f);
        wx *= wi; wy *= wi; wz *= wi;
        float t1 = nax * nmx + nay * nmy + naz * nmz;
        float t3 = rx * nax + ry * nay + rz * naz;
        float t4 = lx * nmx + ly * nmy + lz * nmz;
        float t6 = nax * vx + nay * vy + naz * vz;
        float t7 = nax * wx + nay * wy + naz * wz;
        float cx = nay * nmz - naz * nmy;
        float cy = naz * nmx - nax * nmz;
        float cz = nax * nmy - nay * nmx;
        float t8 = lx * cx + ly * cy + lz * cz;
        const float* cg = &cov[j * 9];
        float s1 = lx * (cg[0] * lx + cg[1] * ly + cg[2] * lz)
                 + ly * (cg[3] * lx + cg[4] * ly + cg[5] * lz)
                 + lz * (cg[6] * lx + cg[7] * ly + cg[8] * lz);
        const float* c0 = &cov[j0 * 9];
        float s2 = lx * (c0[0] * lx + c0[1] * ly + c0[2] * lz)
                 + ly * (c0[3] * lx + c0[4] * ly + c0[5] * lz)
                 + lz * (c0[6] * lx + c0[7] * ly + c0[8] * lz);
        float win[14] = {lx, ly, lz, t1, dot, t3, t4, t3, t6, t7, t8, rn, s1, s2};
        float ya[8];
        #pragma unroll
        for (int o = 0; o < 8; o++) {
            float y = bsm[o];
            #pragma unroll
            for (int c = 0; c < 14; c++) y += wsm[o * 14 + c] * win[c];
            ya[o] = y;
            ls[o] += y; lss[o] += y * y;
        }
        float4* dst = (float4*)&g_y1w[i * 8];
        dst[0] = make_float4(ya[0], ya[1], ya[2], ya[3]);
        dst[1] = make_float4(ya[4], ya[5], ya[6], ya[7]);
    }
    stats_reduce<8>(ls, lss, W1_OFF);
}

// ---------------- w-path layer 2 ----------------
__global__ __launch_bounds__(256) void k_w2(const float* __restrict__ ww2,
                                            const float* __restrict__ wb2) {
    __shared__ float wsm[64], bsm[8], ssc[8], ssh[8];
    int t = threadIdx.x;
    if (t < 64) wsm[t] = ww2[t];
    if (t < 8) { bsm[t] = wb2[t]; ssc[t] = g_ss[W1_OFF + t]; ssh[t] = g_ss[W1_OFF + 8 + t]; }
    __syncthreads();
    float ls[8], lss[8];
    #pragma unroll
    for (int o = 0; o < 8; o++) { ls[o] = 0.f; lss[o] = 0.f; }
    for (int i = blockIdx.x * 256 + t; i < NK; i += gridDim.x * 256) {
        float a[8];
        float4 a0 = *(const float4*)&g_y1w[i * 8];
        float4 a1 = *(const float4*)&g_y1w[i * 8 + 4];
        a[0] = a0.x; a[1] = a0.y; a[2] = a0.z; a[3] = a0.w;
        a[4] = a1.x; a[5] = a1.y; a[6] = a1.z; a[7] = a1.w;
        #pragma unroll
        for (int c = 0; c < 8; c++) a[c] = fmaxf(ssc[c] * a[c] + ssh[c], 0.f);
        float ya[8];
        #pragma unroll
        for (int o = 0; o < 8; o++) {
            float y = bsm[o];
            #pragma unroll
            for (int c = 0; c < 8; c++) y += wsm[o * 8 + c] * a[c];
            ya[o] = y;
            ls[o] += y; lss[o] += y * y;
        }
        float4* dst = (float4*)&g_y2w[i * 8];
        dst[0] = make_float4(ya[0], ya[1], ya[2], ya[3]);
        dst[1] = make_float4(ya[4], ya[5], ya[6], ya[7]);
    }
    stats_reduce<8>(ls, lss, W2_OFF);
}

// ---------------- w-path layer 3: stats only ----------------
__global__ __launch_bounds__(256) void k_w3s(const float* __restrict__ ww3,
                                             const float* __restrict__ wb3) {
    __shared__ float wsm[128], bsm[16], ssc[8], ssh[8];
    int t = threadIdx.x;
    if (t < 128) wsm[t] = ww3[t];
    if (t < 16)  bsm[t] = wb3[t];
    if (t < 8) { ssc[t] = g_ss[W2_OFF + t]; ssh[t] = g_ss[W2_OFF + 8 + t]; }
    __syncthreads();
    float ls[16], lss[16];
    #pragma unroll
    for (int o = 0; o < 16; o++) { ls[o] = 0.f; lss[o] = 0.f; }
    for (int i = blockIdx.x * 256 + t; i < NK; i += gridDim.x * 256) {
        float a[8];
        float4 a0 = *(const float4*)&g_y2w[i * 8];
        float4 a1 = *(const float4*)&g_y2w[i * 8 + 4];
        a[0] = a0.x; a[1] = a0.y; a[2] = a0.z; a[3] = a0.w;
        a[4] = a1.x; a[5] = a1.y; a[6] = a1.z; a[7] = a1.w;
        #pragma unroll
        for (int c = 0; c < 8; c++) a[c] = fmaxf(ssc[c] * a[c] + ssh[c], 0.f);
        #pragma unroll
        for (int o = 0; o < 16; o++) {
            float y = bsm[o];
            #pragma unroll
            for (int c = 0; c < 8; c++) y += wsm[o * 8 + c] * a[c];
            ls[o] += y; lss[o] += y * y;
        }
    }
    stats_reduce<16>(ls, lss, W3_OFF);
}

// ---------------- finalize BN ----------------
__global__ void k_fin(int off, const float* __restrict__ gamma,
                      const float* __restrict__ beta, int nch, float invc) {
    int c = threadIdx.x;
    if (c < nch) {
        float m = g_stats[off + c] * invc;
        float v = g_stats[off + nch + c] * invc - m * m;
        float s = gamma[c] / sqrtf(v + EPS_BN);
        g_ss[off + c] = s;
        g_ss[off + nch + c] = beta[c] - m * s;
    }
}

// ---------------- fpost = half(relu(BN2(g_g2))) ----------------
__global__ void k_post() {
    int i = blockIdx.x * 256 + threadIdx.x;
    if (i < NP * 32) {
        int c = (2 * i) & 63;
        float y0 = g_g2[2 * i],     y1 = g_g2[2 * i + 1];
        y0 = fmaxf(g_ss[F2_OFF + c] * y0 + g_ss[F2_OFF + 64 + c], 0.f);
        y1 = fmaxf(g_ss[F2_OFF + c + 1] * y1 + g_ss[F2_OFF + 64 + c + 1], 0.f);
        *(unsigned*)&g_fph[2 * i] = packh2(y0, y1);
    }
}

// ---------------- new = f @ w^T per point; store half2 words, K-permuted ----------------
__global__ __launch_bounds__(128) void k_new(const int* __restrict__ knn,
                                             const float* __restrict__ ww3,
                                             const float* __restrict__ wb3) {
    __shared__ float sw[256];
    __shared__ int   sj[16];
    __shared__ float sww3[128], swb3[16], sc3[16], sh3[16], sc2[8], sh2[8];
    int t = threadIdx.x, n = blockIdx.x;
    if (t < 128) sww3[t] = ww3[t];
    if (t < 16) {
        swb3[t] = wb3[t];
        sc3[t] = g_ss[W3_OFF + t];
        sh3[t] = g_ss[W3_OFF + 16 + t];
        sj[t] = knn[n * 16 + t];
    }
    if (t >= 16 && t < 24) {
        int c = t - 16;
        sc2[c] = g_ss[W2_OFF + c];
        sh2[c] = g_ss[W2_OFF + 8 + c];
    }
    __syncthreads();
    if (t < 16) {
        int k = t;
        int base = (n * 16 + k) * 8;
        float a[8];
        float4 a0 = *(const float4*)&g_y2w[base];
        float4 a1 = *(const float4*)&g_y2w[base + 4];
        a[0] = a0.x; a[1] = a0.y; a[2] = a0.z; a[3] = a0.w;
        a[4] = a1.x; a[5] = a1.y; a[6] = a1.z; a[7] = a1.w;
        #pragma unroll
        for (int c = 0; c < 8; c++) a[c] = fmaxf(sc2[c] * a[c] + sh2[c], 0.f);
        #pragma unroll
        for (int m = 0; m < 16; m++) {
            float y = swb3[m];
            #pragma unroll
            for (int c = 0; c < 8; c++) y += sww3[m * 8 + c] * a[c];
            sw[m * 16 + k] = fmaxf(sc3[m] * y + sh3[m], 0.f);
        }
    }
    __syncthreads();
    int h = t >> 1, mb = (t & 1) * 8;
    float fv[16];
    #pragma unroll
    for (int k = 0; k < 16; k++)
        fv[k] = __half2float(g_fph[(size_t)sj[k] * 64 + h]);
    float out[8];
    #pragma unroll
    for (int mm = 0; mm < 8; mm++) {
        int m = mb + mm;
        float acc = 0.f;
        #pragma unroll
        for (int k = 0; k < 16; k++) acc += fv[k] * sw[m * 16 + k];
        out[mm] = acc;
    }
    // K-group = h (words h*8..h*8+7). mb=0 -> words 0..3 at pos {0,2,4,6};
    // mb=8 -> words 4..7 at pos {1,3,5,7}.
    unsigned* dst = &g_newh[(size_t)n * 512 + h * 8 + (t & 1)];
    dst[0] = packh2(out[0], out[1]);
    dst[2] = packh2(out[2], out[3]);
    dst[4] = packh2(out[4], out[5]);
    dst[6] = packh2(out[6], out[7]);
}

// ---------------- GEMM: z = new(NPx1024) @ lin_w^T(1024x64), fp16 mma + cp.async ----------------
#define GP 36
#define GA (128*GP)
#define GB (64*GP)
#define SMEM_G ((2*GA + 2*GB)*4)

__global__ __launch_bounds__(256, 3) void k_gemm(const float* __restrict__ lb) {
    extern __shared__ unsigned sm[];
    unsigned* As[2] = { sm, sm + GA };
    unsigned* Bs[2] = { sm + 2 * GA, sm + 2 * GA + GB };
    int t = threadIdx.x;
    int rbase = blockIdx.x * 128;
    int lane = t & 31, grp = lane >> 2, qid = lane & 3;
    int m0 = (t >> 5) * 16;

    if (rbase + 128 > NP) {
        for (int i = t; i < 2 * GA; i += 256) sm[i] = 0u;
        __syncthreads();
    }

    float cf[8][4];
    #pragma unroll
    for (int nt = 0; nt < 8; nt++)
        #pragma unroll
        for (int j = 0; j < 4; j++) cf[nt][j] = 0.f;

    auto load = [&](int buf, int s) {
        int kc = s * 32;  // word offset
        #pragma unroll
        for (int r4 = 0; r4 < 4; r4++) {
            int seg = t + r4 * 256;
            int row = seg >> 3, w16 = seg & 7;
            if (rbase + row < NP)
                cp16(As[buf] + row * GP + w16 * 4,
                     g_newh + (size_t)(rbase + row) * 512 + kc + w16 * 4);
        }
        #pragma unroll
        for (int r2 = 0; r2 < 2; r2++) {
            int seg = t + r2 * 256;
            int row = seg >> 3, w16 = seg & 7;
            cp16(Bs[buf] + row * GP + w16 * 4,
                 g_lwth + row * 512 + kc + w16 * 4);
        }
        asm volatile("cp.async.commit_group;");
    };

    load(0, 0);
    int cur = 0;
    for (int s = 0; s < 16; s++) {
        if (s < 15) {
            load(cur ^ 1, s + 1);
            asm volatile("cp.async.wait_group 1;");
        } else {
            asm volatile("cp.async.wait_group 0;");
        }
        __syncthreads();
        unsigned* A = As[cur];
        unsigned* B = Bs[cur];
        #pragma unroll
        for (int ks = 0; ks < 4; ks++) {
            uint2 aLo = *(uint2*)&A[(m0 + grp) * GP + ks * 8 + qid * 2];
            uint2 aHi = *(uint2*)&A[(m0 + grp + 8) * GP + ks * 8 + qid * 2];
            #pragma unroll
            for (int nt = 0; nt < 8; nt++) {
                uint2 b = *(uint2*)&B[(nt * 8 + grp) * GP + ks * 8 + qid * 2];
                mma_f16(cf[nt], aLo.x, aHi.x, aLo.y, aHi.y, b.x, b.y);
            }
        }
        __syncthreads();
        cur ^= 1;
    }

    int r0 = rbase + m0 + grp, r1 = r0 + 8;
    #pragma unroll
    for (int nt = 0; nt < 8; nt++) {
        int c0 = nt * 8 + 2 * qid;
        float b0v = __ldg(&lb[c0]), b1v = __ldg(&lb[c0 + 1]);
        if (r0 < NP) *(float2*)&g_z[r0 * 64 + c0] = make_float2(cf[nt][0] + b0v, cf[nt][1] + b1v);
        if (r1 < NP) *(float2*)&g_z[r1 * 64 + c0] = make_float2(cf[nt][2] + b0v, cf[nt][3] + b1v);
    }
}

// ---------------- stats over z ----------------
__global__ __launch_bounds__(256) void k_zstats() {
    __shared__ float sred[128];
    int t = threadIdx.x;
    if (t < 128) sred[t] = 0.f;
    __syncthreads();
    int cg = (t & 15) * 4;
    float s[4] = {0.f, 0.f, 0.f, 0.f}, ss[4] = {0.f, 0.f, 0.f, 0.f};
    for (int i = blockIdx.x * 256 + t; i < NP * 16; i += gridDim.x * 256) {
        float4 v = *(const float4*)&g_z[i * 4];
        s[0] += v.x; ss[0] += v.x * v.x;
        s[1] += v.y; ss[1] += v.y * v.y;
        s[2] += v.z; ss[2] += v.z * v.z;
        s[3] += v.w; ss[3] += v.w * v.w;
    }
    const unsigned FULL = 0xffffffffu;
    #pragma unroll
    for (int j = 0; j < 4; j++) {
        s[j]  += __shfl_down_sync(FULL, s[j], 16);
        ss[j] += __shfl_down_sync(FULL, ss[j], 16);
    }
    if ((t & 31) < 16) {
        #pragma unroll
        for (int j = 0; j < 4; j++) {
            atomicAdd(&sred[cg + j], s[j]);
            atomicAdd(&sred[64 + cg + j], ss[j]);
        }
    }
    __syncthreads();
    if (t < 128) atomicAdd(&g_stats[Z_OFF + t], sred[t]);
}

// ---------------- final BN + relu -> output ----------------
__global__ void k_out(float* __restrict__ out) {
    int i = blockIdx.x * 256 + threadIdx.x;
    if (i < NP * 64) {
        int c = i & 63;
        out[i] = fmaxf(g_ss[Z_OFF + c] * g_z[i] + g_ss[Z_OFF + 64 + c], 0.f);
    }
}

// ---------------- launch ----------------
extern "C" void kernel_launch(void* const* d_in, const int* in_sizes, int n_in,
                              void* d_out, int out_size) {
    const float* xyz   = (const float*)d_in[0];
    const float* cov   = (const float*)d_in[1];
    const float* feats = (const float*)d_in[2];
    const int*   knn   = (const int*)  d_in[3];
    const float* fw1 = (const float*)d_in[4];
    const float* fb1 = (const float*)d_in[5];
    const float* fg1 = (const float*)d_in[6];
    const float* fbe1 = (const float*)d_in[7];
    const float* fw2 = (const float*)d_in[8];
    const float* fb2 = (const float*)d_in[9];
    const float* fg2 = (const float*)d_in[10];
    const float* fbe2 = (const float*)d_in[11];
    const float* ww1 = (const float*)d_in[12];
    const float* wb1 = (const float*)d_in[13];
    const float* wg1 = (const float*)d_in[14];
    const float* wbe1 = (const float*)d_in[15];
    const float* ww2 = (const float*)d_in[16];
    const float* wb2 = (const float*)d_in[17];
    const float* wg2 = (const float*)d_in[18];
    const float* wbe2 = (const float*)d_in[19];
    const float* ww3 = (const float*)d_in[20];
    const float* wb3 = (const float*)d_in[21];
    const float* wg3 = (const float*)d_in[22];
    const float* wbe3 = (const float*)d_in[23];
    const float* lin_w = (const float*)d_in[24];
    const float* lin_b = (const float*)d_in[25];
    const float* bng = (const float*)d_in[26];
    const float* bnb = (const float*)d_in[27];
    float* out = (float*)d_out;

    const float invNK = 1.f / (float)NK;
    const float invN  = 1.f / (float)NP;
    const int NBLK = (NP + 127) / 128;

    float* d_g1; cudaGetSymbolAddress((void**)&d_g1, g_g1);
    float* d_g2; cudaGetSymbolAddress((void**)&d_g2, g_g2);
    unsigned* d_fh;  cudaGetSymbolAddress((void**)&d_fh,  g_fh);
    unsigned* d_g1h; cudaGetSymbolAddress((void**)&d_g1h, g_g1h);
    unsigned* d_w1h; cudaGetSymbolAddress((void**)&d_w1h, g_w1h);
    unsigned* d_w2h; cudaGetSymbolAddress((void**)&d_w2h, g_w2h);

    cudaFuncSetAttribute(k_gemm, cudaFuncAttributeMaxDynamicSharedMemorySize, SMEM_G);

    k_zero<<<(NP + 255) / 256, 256>>>();
    k_cnt<<<(NK + 255) / 256, 256>>>(knn);
    k_preph<<<128, 256>>>(lin_w);
    k_prepw<<<16, 256>>>(fw1, fw2);
    k_prepf<<<(NP * 32 + 255) / 256, 256>>>(feats);

    // stage 1
    k_fmma<<<NBLK, 256>>>(d_fh, d_w1h, fb1, d_g1, F1_OFF);
    k_w1<<<2048, 256>>>(xyz, cov, feats, knn, ww1, wb1);
    k_fin<<<1, 64>>>(F1_OFF, fg1, fbe1, 64, invNK);
    k_fin<<<1, 64>>>(W1_OFF, wg1, wbe1, 8, invNK);

    // stage 2
    k_mid<<<(NP * 32 + 255) / 256, 256>>>();
    k_fmma<<<NBLK, 256>>>(d_g1h, d_w2h, fb2, d_g2, F2_OFF);
    k_w2<<<2048, 256>>>(ww2, wb2);
    k_fin<<<1, 64>>>(F2_OFF, fg2, fbe2, 64, invNK);
    k_fin<<<1, 64>>>(W2_OFF, wg2, wbe2, 8, invNK);

    // fpost + stage 3 (w path)
    k_post<<<(NP * 32 + 255) / 256, 256>>>();
    k_w3s<<<2048, 256>>>(ww3, wb3);
    k_fin<<<1, 64>>>(W3_OFF, wg3, wbe3, 16, invNK);

    // einsum + GEMM + final BN
    k_new<<<NP, 128>>>(knn, ww3, wb3);
    k_gemm<<<NBLK, 256, SMEM_G>>>(lin_b);
    k_zstats<<<512, 256>>>();
    k_fin<<<1, 64>>>(Z_OFF, bng, bnb, 64, invN);
    k_out<<<(NP * 64 + 255) / 256, 256>>>(out);
}

// round 6
// speedup vs baseline: 1.2994x; 1.2994x over previous
#include <cuda_runtime.h>
#include <cuda_fp16.h>

#define NP 100000
#define KN 16
#define NK (NP*KN)

// ---------------- device scratch ----------------
__device__ int      g_cnt[NP];
__device__ float    g_g1[NP*64];          // f-path layer1 pre-BN (fp32)
__device__ float    g_g2[NP*64];          // f-path layer2 pre-BN (fp32)
__device__ unsigned g_fh[NP*32];          // feats as half2 words, K-permuted
__device__ unsigned g_g1h[NP*32];         // relu(BN1(g1)) as half2 words, K-permuted
__device__ __align__(16) __half g_fph[NP*64];  // fpost = relu(BN2(g2)) fp16, linear
__device__ unsigned g_w1h[64*32];         // fw1 half2, K-permuted
__device__ unsigned g_w2h[64*32];         // fw2 half2, K-permuted
__device__ float    g_y1w[NK*8];
__device__ float    g_y2w[NK*8];
__device__ unsigned g_newh[NP*512];       // new_flat as half2 words, K-permuted
__device__ unsigned g_lwth[64*512];       // lin_w as half2 words, K-permuted
__device__ float    g_z[NP*64];
__device__ float    g_stats[448];
__device__ float    g_ss[448];

#define F1_OFF 0
#define W1_OFF 128
#define F2_OFF 144
#define W2_OFF 272
#define W3_OFF 288
#define Z_OFF  320

#define EPS_BN 1e-5f

// ---------------- init ----------------
__global__ void k_zero() {
    int i = blockIdx.x * 256 + threadIdx.x;
    if (i < NP)  g_cnt[i] = 0;
    if (i < 448) g_stats[i] = 0.f;
}

__global__ void k_cnt(const int* __restrict__ knn) {
    int i = blockIdx.x * 256 + threadIdx.x;
    if (i < NK) atomicAdd(&g_cnt[knn[i]], 1);
}

// ---------------- stats helper ----------------
template<int CH>
__device__ __forceinline__ void stats_reduce(float* ls, float* lss, int off) {
    const unsigned FULL = 0xffffffffu;
    #pragma unroll
    for (int c = 0; c < CH; c++) {
        #pragma unroll
        for (int o = 16; o; o >>= 1) {
            ls[c]  += __shfl_down_sync(FULL, ls[c],  o);
            lss[c] += __shfl_down_sync(FULL, lss[c], o);
        }
    }
    __shared__ float sred[2 * 8 * CH];
    int wid = threadIdx.x >> 5, lane = threadIdx.x & 31;
    if (lane == 0) {
        #pragma unroll
        for (int c = 0; c < CH; c++) {
            sred[wid * CH + c]          = ls[c];
            sred[8 * CH + wid * CH + c] = lss[c];
        }
    }
    __syncthreads();
    if (threadIdx.x < CH) {
        float a = 0.f, b = 0.f;
        #pragma unroll
        for (int w = 0; w < 8; w++) {
            a += sred[w * CH + threadIdx.x];
            b += sred[8 * CH + w * CH + threadIdx.x];
        }
        atomicAdd(&g_stats[off + threadIdx.x], a);
        atomicAdd(&g_stats[off + CH + threadIdx.x], b);
    }
}

// ---------------- fp16 helpers ----------------
__device__ __forceinline__ unsigned packh2(float a, float b) {
    __half2 h = __floats2half2_rn(a, b);
    return *(unsigned*)&h;
}

__device__ __forceinline__ void mma_f16(float* c, unsigned a0, unsigned a1,
                                        unsigned a2, unsigned a3,
                                        unsigned b0, unsigned b1) {
    asm volatile("mma.sync.aligned.m16n8k16.row.col.f32.f16.f16.f32 "
                 "{%0,%1,%2,%3}, {%4,%5,%6,%7}, {%8,%9}, {%0,%1,%2,%3};"
                 : "+f"(c[0]), "+f"(c[1]), "+f"(c[2]), "+f"(c[3])
                 : "r"(a0), "r"(a1), "r"(a2), "r"(a3), "r"(b0), "r"(b1));
}

__device__ __forceinline__ void cp16(void* sptr, const void* gptr) {
    unsigned saddr = (unsigned)__cvta_generic_to_shared(sptr);
    asm volatile("cp.async.cg.shared.global [%0], [%1], 16;" :: "r"(saddr), "l"(gptr));
}

__device__ __forceinline__ unsigned smem_u32x(const void* p) {
    return (unsigned)__cvta_generic_to_shared(p);
}

__device__ __forceinline__ void ldsm_x4_trans(unsigned& r0, unsigned& r1,
                                              unsigned& r2, unsigned& r3, unsigned addr) {
    asm volatile("ldmatrix.sync.aligned.m8n8.x4.trans.shared.b16 {%0,%1,%2,%3}, [%4];"
                 : "=r"(r0), "=r"(r1), "=r"(r2), "=r"(r3) : "r"(addr));
}

__device__ __forceinline__ void ldsm_x2(unsigned& r0, unsigned& r1, unsigned addr) {
    asm volatile("ldmatrix.sync.aligned.m8n8.x2.shared.b16 {%0,%1}, [%2];"
                 : "=r"(r0), "=r"(r1) : "r"(addr));
}

__device__ __forceinline__ int wperm(int j) {   // word pos within 8-word k-group
    return ((j & 3) << 1) | (j >> 2);
}

// ---------------- preps: fp32 -> half2 words, K-permuted ----------------
__global__ void k_prepf(const float* __restrict__ src) {   // feats -> g_fh
    int i = blockIdx.x * 256 + threadIdx.x;
    if (i < NP * 32) {
        int row = i >> 5, W = i & 31;
        unsigned v = packh2(src[row * 64 + 2 * W], src[row * 64 + 2 * W + 1]);
        g_fh[row * 32 + (W & ~7) + wperm(W & 7)] = v;
    }
}

__global__ void k_prepw(const float* __restrict__ w1, const float* __restrict__ w2) {
    int i = blockIdx.x * 256 + threadIdx.x;
    if (i < 2 * 64 * 32) {
        const float* src = (i < 64 * 32) ? w1 : w2;
        unsigned* dst = (i < 64 * 32) ? g_w1h : g_w2h;
        int r = i & (64 * 32 - 1);
        int row = r >> 5, W = r & 31;
        unsigned v = packh2(src[row * 64 + 2 * W], src[row * 64 + 2 * W + 1]);
        dst[row * 32 + (W & ~7) + wperm(W & 7)] = v;
    }
}

__global__ void k_preph(const float* __restrict__ lw) {   // lin_w -> g_lwth
    int i = blockIdx.x * 256 + threadIdx.x;
    if (i < 64 * 512) {
        int row = i >> 9, W = i & 511;
        unsigned v = packh2(lw[row * 1024 + 2 * W], lw[row * 1024 + 2 * W + 1]);
        g_lwth[row * 512 + (W & ~7) + wperm(W & 7)] = v;
    }
}

// ---------------- mid: g1h = half(relu(BN1(g_g1))), K-permuted ----------------
__global__ void k_mid() {
    int i = blockIdx.x * 256 + threadIdx.x;
    if (i < NP * 32) {
        int row = i >> 5, W = i & 31;
        int c = 2 * W;
        float y0 = g_g1[row * 64 + c], y1 = g_g1[row * 64 + c + 1];
        y0 = fmaxf(g_ss[F1_OFF + c] * y0 + g_ss[F1_OFF + 64 + c], 0.f);
        y1 = fmaxf(g_ss[F1_OFF + c + 1] * y1 + g_ss[F1_OFF + 64 + c + 1], 0.f);
        g_g1h[row * 32 + (W & ~7) + wperm(W & 7)] = packh2(y0, y1);
    }
}

// ---------------- f-path conv via fp16 mma ----------------
#define FP 36
#define FA (128*FP)
#define FB (64*FP)

__global__ __launch_bounds__(256) void k_fmma(const unsigned* __restrict__ inH,
                                              const unsigned* __restrict__ wH,
                                              const float* __restrict__ B,
                                              float* __restrict__ dst,
                                              int statoff) {
    __shared__ unsigned As[FA];
    __shared__ unsigned Bs[FB];
    __shared__ float sred[128];
    int t = threadIdx.x;
    int rbase = blockIdx.x * 128;
    int lane = t & 31, grp = lane >> 2, qid = lane & 3;
    int m0 = (t >> 5) * 16;

    if (rbase + 128 > NP) {
        for (int i = t; i < FA; i += 256) As[i] = 0u;
        __syncthreads();
    }
    if (t < 128) sred[t] = 0.f;

    #pragma unroll
    for (int r4 = 0; r4 < 4; r4++) {
        int seg = t + r4 * 256;
        int row = seg >> 3, w16 = seg & 7;
        if (rbase + row < NP)
            cp16(As + row * FP + w16 * 4, inH + (size_t)(rbase + row) * 32 + w16 * 4);
    }
    #pragma unroll
    for (int r2 = 0; r2 < 2; r2++) {
        int seg = t + r2 * 256;
        int row = seg >> 3, w16 = seg & 7;
        cp16(Bs + row * FP + w16 * 4, wH + row * 32 + w16 * 4);
    }
    asm volatile("cp.async.commit_group;");
    asm volatile("cp.async.wait_group 0;");
    __syncthreads();

    float cf[8][4];
    #pragma unroll
    for (int nt = 0; nt < 8; nt++)
        #pragma unroll
        for (int j = 0; j < 4; j++) cf[nt][j] = 0.f;

    #pragma unroll
    for (int ks = 0; ks < 4; ks++) {
        uint2 aLo = *(uint2*)&As[(m0 + grp) * FP + ks * 8 + qid * 2];
        uint2 aHi = *(uint2*)&As[(m0 + grp + 8) * FP + ks * 8 + qid * 2];
        #pragma unroll
        for (int nt = 0; nt < 8; nt++) {
            uint2 b = *(uint2*)&Bs[(nt * 8 + grp) * FP + ks * 8 + qid * 2];
            mma_f16(cf[nt], aLo.x, aHi.x, aLo.y, aHi.y, b.x, b.y);
        }
    }

    int r0 = rbase + m0 + grp, r1 = r0 + 8;
    float w0 = (r0 < NP) ? (float)g_cnt[r0] : 0.f;
    float w1v = (r1 < NP) ? (float)g_cnt[r1] : 0.f;
    #pragma unroll
    for (int nt = 0; nt < 8; nt++) {
        int c0 = nt * 8 + 2 * qid;
        float b0v = __ldg(&B[c0]), b1v = __ldg(&B[c0 + 1]);
        float z0 = cf[nt][0] + b0v, z1 = cf[nt][1] + b1v;
        float z2 = cf[nt][2] + b0v, z3 = cf[nt][3] + b1v;
        if (r0 < NP) *(float2*)&dst[(size_t)r0 * 64 + c0] = make_float2(z0, z1);
        if (r1 < NP) *(float2*)&dst[(size_t)r1 * 64 + c0] = make_float2(z2, z3);
        atomicAdd(&sred[c0],     w0 * z0 + w1v * z2);
        atomicAdd(&sred[c0 + 1], w0 * z1 + w1v * z3);
        atomicAdd(&sred[64 + c0],     w0 * z0 * z0 + w1v * z2 * z2);
        atomicAdd(&sred[64 + c0 + 1], w0 * z1 * z1 + w1v * z3 * z3);
    }
    __syncthreads();
    if (t < 128) atomicAdd(&g_stats[statoff + t], sred[t]);
}

// ---------------- w-path layer 1 ----------------
__global__ __launch_bounds__(256, 3) void k_w1(const float* __restrict__ xyz,
                                               const float* __restrict__ cov,
                                               const float* __restrict__ feats,
                                               const int* __restrict__ knn,
                                               const float* __restrict__ ww1,
                                               const float* __restrict__ wb1) {
    __shared__ float wsm[112];
    __shared__ float bsm[8];
    int t = threadIdx.x;
    if (t < 112) wsm[t] = ww1[t];
    if (t < 8)   bsm[t] = wb1[t];
    __syncthreads();
    float ls[8], lss[8];
    #pragma unroll
    for (int o = 0; o < 8; o++) { ls[o] = 0.f; lss[o] = 0.f; }
    for (int i = blockIdx.x * 256 + t; i < NK; i += gridDim.x * 256) {
        int n = i >> 4;
        int j  = knn[i];
        int j0 = knn[n << 4];
        float lx = xyz[j * 3 + 0] - xyz[j0 * 3 + 0];
        float ly = xyz[j * 3 + 1] - xyz[j0 * 3 + 1];
        float lz = xyz[j * 3 + 2] - xyz[j0 * 3 + 2];
        float nax = feats[j * 64 + 3],  nay = feats[j * 64 + 4],  naz = feats[j * 64 + 5];
        float nmx = feats[j0 * 64 + 3], nmy = feats[j0 * 64 + 4], nmz = feats[j0 * 64 + 5];
        float rn = sqrtf(lx * lx + ly * ly + lz * lz);
        float inv = 1.f / fmaxf(rn, 1e-12f);
        float rx = lx * inv, ry = ly * inv, rz = lz * inv;
        float dot = nmx * rx + nmy * ry + nmz * rz;
        float vx = nmx - dot * rx, vy = nmy - dot * ry, vz = nmz - dot * rz;
        float vi = 1.f / fmaxf(sqrtf(vx * vx + vy * vy + vz * vz), 1e-12f);
        vx *= vi; vy *= vi; vz *= vi;
        float wx = ry * vz - rz * vy;
        float wy = rz * vx - rx * vz;
        float wz = rx * vy - ry * vx;
        float wi = 1.f / fmaxf(sqrtf(wx * wx + wy * wy + wz * wz), 1e-12f);
        wx *= wi; wy *= wi; wz *= wi;
        float t1 = nax * nmx + nay * nmy + naz * nmz;
        float t3 = rx * nax + ry * nay + rz * naz;
        float t4 = lx * nmx + ly * nmy + lz * nmz;
        float t6 = nax * vx + nay * vy + naz * vz;
        float t7 = nax * wx + nay * wy + naz * wz;
        float cx = nay * nmz - naz * nmy;
        float cy = naz * nmx - nax * nmz;
        float cz = nax * nmy - nay * nmx;
        float t8 = lx * cx + ly * cy + lz * cz;
        const float* cg = &cov[j * 9];
        float s1 = lx * (cg[0] * lx + cg[1] * ly + cg[2] * lz)
                 + ly * (cg[3] * lx + cg[4] * ly + cg[5] * lz)
                 + lz * (cg[6] * lx + cg[7] * ly + cg[8] * lz);
        const float* c0 = &cov[j0 * 9];
        float s2 = lx * (c0[0] * lx + c0[1] * ly + c0[2] * lz)
                 + ly * (c0[3] * lx + c0[4] * ly + c0[5] * lz)
                 + lz * (c0[6] * lx + c0[7] * ly + c0[8] * lz);
        float win[14] = {lx, ly, lz, t1, dot, t3, t4, t3, t6, t7, t8, rn, s1, s2};
        float ya[8];
        #pragma unroll
        for (int o = 0; o < 8; o++) {
            float y = bsm[o];
            #pragma unroll
            for (int c = 0; c < 14; c++) y += wsm[o * 14 + c] * win[c];
            ya[o] = y;
            ls[o] += y; lss[o] += y * y;
        }
        float4* dst = (float4*)&g_y1w[i * 8];
        dst[0] = make_float4(ya[0], ya[1], ya[2], ya[3]);
        dst[1] = make_float4(ya[4], ya[5], ya[6], ya[7]);
    }
    stats_reduce<8>(ls, lss, W1_OFF);
}

// ---------------- w-path layer 2 ----------------
__global__ __launch_bounds__(256) void k_w2(const float* __restrict__ ww2,
                                            const float* __restrict__ wb2) {
    __shared__ float wsm[64], bsm[8], ssc[8], ssh[8];
    int t = threadIdx.x;
    if (t < 64) wsm[t] = ww2[t];
    if (t < 8) { bsm[t] = wb2[t]; ssc[t] = g_ss[W1_OFF + t]; ssh[t] = g_ss[W1_OFF + 8 + t]; }
    __syncthreads();
    float ls[8], lss[8];
    #pragma unroll
    for (int o = 0; o < 8; o++) { ls[o] = 0.f; lss[o] = 0.f; }
    for (int i = blockIdx.x * 256 + t; i < NK; i += gridDim.x * 256) {
        float a[8];
        float4 a0 = *(const float4*)&g_y1w[i * 8];
        float4 a1 = *(const float4*)&g_y1w[i * 8 + 4];
        a[0] = a0.x; a[1] = a0.y; a[2] = a0.z; a[3] = a0.w;
        a[4] = a1.x; a[5] = a1.y; a[6] = a1.z; a[7] = a1.w;
        #pragma unroll
        for (int c = 0; c < 8; c++) a[c] = fmaxf(ssc[c] * a[c] + ssh[c], 0.f);
        float ya[8];
        #pragma unroll
        for (int o = 0; o < 8; o++) {
            float y = bsm[o];
            #pragma unroll
            for (int c = 0; c < 8; c++) y += wsm[o * 8 + c] * a[c];
            ya[o] = y;
            ls[o] += y; lss[o] += y * y;
        }
        float4* dst = (float4*)&g_y2w[i * 8];
        dst[0] = make_float4(ya[0], ya[1], ya[2], ya[3]);
        dst[1] = make_float4(ya[4], ya[5], ya[6], ya[7]);
    }
    stats_reduce<8>(ls, lss, W2_OFF);
}

// ---------------- w-path layer 3: stats only ----------------
__global__ __launch_bounds__(256) void k_w3s(const float* __restrict__ ww3,
                                             const float* __restrict__ wb3) {
    __shared__ float wsm[128], bsm[16], ssc[8], ssh[8];
    int t = threadIdx.x;
    if (t < 128) wsm[t] = ww3[t];
    if (t < 16)  bsm[t] = wb3[t];
    if (t < 8) { ssc[t] = g_ss[W2_OFF + t]; ssh[t] = g_ss[W2_OFF + 8 + t]; }
    __syncthreads();
    float ls[16], lss[16];
    #pragma unroll
    for (int o = 0; o < 16; o++) { ls[o] = 0.f; lss[o] = 0.f; }
    for (int i = blockIdx.x * 256 + t; i < NK; i += gridDim.x * 256) {
        float a[8];
        float4 a0 = *(const float4*)&g_y2w[i * 8];
        float4 a1 = *(const float4*)&g_y2w[i * 8 + 4];
        a[0] = a0.x; a[1] = a0.y; a[2] = a0.z; a[3] = a0.w;
        a[4] = a1.x; a[5] = a1.y; a[6] = a1.z; a[7] = a1.w;
        #pragma unroll
        for (int c = 0; c < 8; c++) a[c] = fmaxf(ssc[c] * a[c] + ssh[c], 0.f);
        #pragma unroll
        for (int o = 0; o < 16; o++) {
            float y = bsm[o];
            #pragma unroll
            for (int c = 0; c < 8; c++) y += wsm[o * 8 + c] * a[c];
            ls[o] += y; lss[o] += y * y;
        }
    }
    stats_reduce<16>(ls, lss, W3_OFF);
}

// ---------------- finalize BN ----------------
__global__ void k_fin(int off, const float* __restrict__ gamma,
                      const float* __restrict__ beta, int nch, float invc) {
    int c = threadIdx.x;
    if (c < nch) {
        float m = g_stats[off + c] * invc;
        float v = g_stats[off + nch + c] * invc - m * m;
        float s = gamma[c] / sqrtf(v + EPS_BN);
        g_ss[off + c] = s;
        g_ss[off + nch + c] = beta[c] - m * s;
    }
}

// ---------------- fpost = half(relu(BN2(g_g2))) ----------------
__global__ void k_post() {
    int i = blockIdx.x * 256 + threadIdx.x;
    if (i < NP * 32) {
        int c = (2 * i) & 63;
        float y0 = g_g2[2 * i],     y1 = g_g2[2 * i + 1];
        y0 = fmaxf(g_ss[F2_OFF + c] * y0 + g_ss[F2_OFF + 64 + c], 0.f);
        y1 = fmaxf(g_ss[F2_OFF + c + 1] * y1 + g_ss[F2_OFF + 64 + c + 1], 0.f);
        *(unsigned*)&g_fph[2 * i] = packh2(y0, y1);
    }
}

// ---------------- new = f @ w^T per point, TENSOR CORE version ----------------
// warp = 1 point. A = fpost_gathered^T (64h x 16k) via ldmatrix.trans,
// B = w (16m x 16k) via ldmatrix. 8x mma.m16n8k16 -> D(64x16) fp32,
// stored directly in the K-permuted half2 layout k_gemm consumes.
__global__ __launch_bounds__(256) void k_newmma(const int* __restrict__ knn,
                                                const float* __restrict__ ww3,
                                                const float* __restrict__ wb3) {
    __shared__ __align__(16) __half st[8][16 * 72];   // [warp][k][h], 144B row stride
    __shared__ __align__(16) __half ws[8][16 * 24];   // [warp][m][k], 48B row stride
    __shared__ float sww3[128], swb3[16], sc3[16], sh3[16], sc2[8], sh2[8];
    int t = threadIdx.x, w = t >> 5, l = t & 31;
    if (t < 128) sww3[t] = ww3[t];
    if (t < 16) {
        swb3[t] = wb3[t];
        sc3[t] = g_ss[W3_OFF + t];
        sh3[t] = g_ss[W3_OFF + 16 + t];
    }
    if (t >= 16 && t < 24) {
        int c = t - 16;
        sc2[c] = g_ss[W2_OFF + c];
        sh2[c] = g_ss[W2_OFF + 8 + c];
    }
    __syncthreads();

    int n = blockIdx.x * 8 + w;
    int sjv = knn[n * 16 + (l & 15)];
    int jj = __shfl_sync(0xffffffffu, sjv, l >> 1);

    // stage fpost: lane l loads 64B half-row (l&1) of neighbor l>>1
    {
        const uint4* src = (const uint4*)(g_fph + (size_t)jj * 64 + (l & 1) * 32);
        uint4* dst = (uint4*)&st[w][(l >> 1) * 72 + (l & 1) * 32];
        dst[0] = src[0]; dst[1] = src[1]; dst[2] = src[2]; dst[3] = src[3];
    }

    // w tile: lane k computes column k (16 m values), BN2+relu then conv3+BN3+relu
    if (l < 16) {
        int base = (n * 16 + l) * 8;
        float a[8];
        float4 a0 = *(const float4*)&g_y2w[base];
        float4 a1 = *(const float4*)&g_y2w[base + 4];
        a[0] = a0.x; a[1] = a0.y; a[2] = a0.z; a[3] = a0.w;
        a[4] = a1.x; a[5] = a1.y; a[6] = a1.z; a[7] = a1.w;
        #pragma unroll
        for (int c = 0; c < 8; c++) a[c] = fmaxf(sc2[c] * a[c] + sh2[c], 0.f);
        #pragma unroll
        for (int m = 0; m < 16; m++) {
            float y = swb3[m];
            #pragma unroll
            for (int c = 0; c < 8; c++) y += sww3[m * 8 + c] * a[c];
            ws[w][m * 24 + l] = __float2half(fmaxf(sc3[m] * y + sh3[m], 0.f));
        }
    }
    __syncwarp();

    // B fragments (w): n8k16 per mg
    unsigned bf[2][2];
    #pragma unroll
    for (int mg = 0; mg < 2; mg++) {
        int q = l & 15;
        unsigned addr = smem_u32x(&ws[w][(mg * 8 + (q & 7)) * 24 + (q >> 3) * 8]);
        ldsm_x2(bf[mg][0], bf[mg][1], addr);
    }

    float d[4][2][4] = {};

    // A lane addressing: mat0 k0-7/h0-7, mat1 k0-7/h8-15, mat2 k8-15/h0-7, mat3 k8-15/h8-15
    int matid = l >> 3;
    int krow = (l & 7) + ((matid >> 1) << 3);
    int coff = (matid & 1) * 8;

    #pragma unroll
    for (int hg = 0; hg < 4; hg++) {
        unsigned a0, a1, a2, a3;
        unsigned addr = smem_u32x(&st[w][krow * 72 + hg * 16 + coff]);
        ldsm_x4_trans(a0, a1, a2, a3, addr);
        #pragma unroll
        for (int mg = 0; mg < 2; mg++)
            mma_f16(d[hg][mg], a0, a1, a2, a3, bf[mg][0], bf[mg][1]);
    }

    // store D -> g_newh in K-permuted half2 layout
    int g = l >> 2, tt = l & 3;
    unsigned* row = g_newh + (size_t)n * 512;
    #pragma unroll
    for (int hg = 0; hg < 4; hg++) {
        int h = hg * 16 + g;
        #pragma unroll
        for (int mg = 0; mg < 2; mg++) {
            int pos = wperm(mg * 4 + tt);
            row[h * 8 + pos]       = packh2(d[hg][mg][0], d[hg][mg][1]);
            row[(h + 8) * 8 + pos] = packh2(d[hg][mg][2], d[hg][mg][3]);
        }
    }
}

// ---------------- GEMM: z = new(NPx1024) @ lin_w^T(1024x64), fp16 mma + cp.async ----------------
#define GP 36
#define GA (128*GP)
#define GB (64*GP)
#define SMEM_G ((2*GA + 2*GB)*4)

__global__ __launch_bounds__(256, 3) void k_gemm(const float* __restrict__ lb) {
    extern __shared__ unsigned sm[];
    unsigned* As[2] = { sm, sm + GA };
    unsigned* Bs[2] = { sm + 2 * GA, sm + 2 * GA + GB };
    int t = threadIdx.x;
    int rbase = blockIdx.x * 128;
    int lane = t & 31, grp = lane >> 2, qid = lane & 3;
    int m0 = (t >> 5) * 16;

    if (rbase + 128 > NP) {
        for (int i = t; i < 2 * GA; i += 256) sm[i] = 0u;
        __syncthreads();
    }

    float cf[8][4];
    #pragma unroll
    for (int nt = 0; nt < 8; nt++)
        #pragma unroll
        for (int j = 0; j < 4; j++) cf[nt][j] = 0.f;

    auto load = [&](int buf, int s) {
        int kc = s * 32;
        #pragma unroll
        for (int r4 = 0; r4 < 4; r4++) {
            int seg = t + r4 * 256;
            int row = seg >> 3, w16 = seg & 7;
            if (rbase + row < NP)
                cp16(As[buf] + row * GP + w16 * 4,
                     g_newh + (size_t)(rbase + row) * 512 + kc + w16 * 4);
        }
        #pragma unroll
        for (int r2 = 0; r2 < 2; r2++) {
            int seg = t + r2 * 256;
            int row = seg >> 3, w16 = seg & 7;
            cp16(Bs[buf] + row * GP + w16 * 4,
                 g_lwth + row * 512 + kc + w16 * 4);
        }
        asm volatile("cp.async.commit_group;");
    };

    load(0, 0);
    int cur = 0;
    for (int s = 0; s < 16; s++) {
        if (s < 15) {
            load(cur ^ 1, s + 1);
            asm volatile("cp.async.wait_group 1;");
        } else {
            asm volatile("cp.async.wait_group 0;");
        }
        __syncthreads();
        unsigned* A = As[cur];
        unsigned* B = Bs[cur];
        #pragma unroll
        for (int ks = 0; ks < 4; ks++) {
            uint2 aLo = *(uint2*)&A[(m0 + grp) * GP + ks * 8 + qid * 2];
            uint2 aHi = *(uint2*)&A[(m0 + grp + 8) * GP + ks * 8 + qid * 2];
            #pragma unroll
            for (int nt = 0; nt < 8; nt++) {
                uint2 b = *(uint2*)&B[(nt * 8 + grp) * GP + ks * 8 + qid * 2];
                mma_f16(cf[nt], aLo.x, aHi.x, aLo.y, aHi.y, b.x, b.y);
            }
        }
        __syncthreads();
        cur ^= 1;
    }

    int r0 = rbase + m0 + grp, r1 = r0 + 8;
    #pragma unroll
    for (int nt = 0; nt < 8; nt++) {
        int c0 = nt * 8 + 2 * qid;
        float b0v = __ldg(&lb[c0]), b1v = __ldg(&lb[c0 + 1]);
        if (r0 < NP) *(float2*)&g_z[r0 * 64 + c0] = make_float2(cf[nt][0] + b0v, cf[nt][1] + b1v);
        if (r1 < NP) *(float2*)&g_z[r1 * 64 + c0] = make_float2(cf[nt][2] + b0v, cf[nt][3] + b1v);
    }
}

// ---------------- stats over z ----------------
__global__ __launch_bounds__(256) void k_zstats() {
    __shared__ float sred[128];
    int t = threadIdx.x;
    if (t < 128) sred[t] = 0.f;
    __syncthreads();
    int cg = (t & 15) * 4;
    float s[4] = {0.f, 0.f, 0.f, 0.f}, ss[4] = {0.f, 0.f, 0.f, 0.f};
    for (int i = blockIdx.x * 256 + t; i < NP * 16; i += gridDim.x * 256) {
        float4 v = *(const float4*)&g_z[i * 4];
        s[0] += v.x; ss[0] += v.x * v.x;
        s[1] += v.y; ss[1] += v.y * v.y;
        s[2] += v.z; ss[2] += v.z * v.z;
        s[3] += v.w; ss[3] += v.w * v.w;
    }
    const unsigned FULL = 0xffffffffu;
    #pragma unroll
    for (int j = 0; j < 4; j++) {
        s[j]  += __shfl_down_sync(FULL, s[j], 16);
        ss[j] += __shfl_down_sync(FULL, ss[j], 16);
    }
    if ((t & 31) < 16) {
        #pragma unroll
        for (int j = 0; j < 4; j++) {
            atomicAdd(&sred[cg + j], s[j]);
            atomicAdd(&sred[64 + cg + j], ss[j]);
        }
    }
    __syncthreads();
    if (t < 128) atomicAdd(&g_stats[Z_OFF + t], sred[t]);
}

// ---------------- final BN + relu -> output ----------------
__global__ void k_out(float* __restrict__ out) {
    int i = blockIdx.x * 256 + threadIdx.x;
    if (i < NP * 64) {
        int c = i & 63;
        out[i] = fmaxf(g_ss[Z_OFF + c] * g_z[i] + g_ss[Z_OFF + 64 + c], 0.f);
    }
}

// ---------------- launch ----------------
extern "C" void kernel_launch(void* const* d_in, const int* in_sizes, int n_in,
                              void* d_out, int out_size) {
    const float* xyz   = (const float*)d_in[0];
    const float* cov   = (const float*)d_in[1];
    const float* feats = (const float*)d_in[2];
    const int*   knn   = (const int*)  d_in[3];
    const float* fw1 = (const float*)d_in[4];
    const float* fb1 = (const float*)d_in[5];
    const float* fg1 = (const float*)d_in[6];
    const float* fbe1 = (const float*)d_in[7];
    const float* fw2 = (const float*)d_in[8];
    const float* fb2 = (const float*)d_in[9];
    const float* fg2 = (const float*)d_in[10];
    const float* fbe2 = (const float*)d_in[11];
    const float* ww1 = (const float*)d_in[12];
    const float* wb1 = (const float*)d_in[13];
    const float* wg1 = (const float*)d_in[14];
    const float* wbe1 = (const float*)d_in[15];
    const float* ww2 = (const float*)d_in[16];
    const float* wb2 = (const float*)d_in[17];
    const float* wg2 = (const float*)d_in[18];
    const float* wbe2 = (const float*)d_in[19];
    const float* ww3 = (const float*)d_in[20];
    const float* wb3 = (const float*)d_in[21];
    const float* wg3 = (const float*)d_in[22];
    const float* wbe3 = (const float*)d_in[23];
    const float* lin_w = (const float*)d_in[24];
    const float* lin_b = (const float*)d_in[25];
    const float* bng = (const float*)d_in[26];
    const float* bnb = (const float*)d_in[27];
    float* out = (float*)d_out;

    const float invNK = 1.f / (float)NK;
    const float invN  = 1.f / (float)NP;
    const int NBLK = (NP + 127) / 128;

    float* d_g1; cudaGetSymbolAddress((void**)&d_g1, g_g1);
    float* d_g2; cudaGetSymbolAddress((void**)&d_g2, g_g2);
    unsigned* d_fh;  cudaGetSymbolAddress((void**)&d_fh,  g_fh);
    unsigned* d_g1h; cudaGetSymbolAddress((void**)&d_g1h, g_g1h);
    unsigned* d_w1h; cudaGetSymbolAddress((void**)&d_w1h, g_w1h);
    unsigned* d_w2h; cudaGetSymbolAddress((void**)&d_w2h, g_w2h);

    cudaFuncSetAttribute(k_gemm, cudaFuncAttributeMaxDynamicSharedMemorySize, SMEM_G);

    k_zero<<<(NP + 255) / 256, 256>>>();
    k_cnt<<<(NK + 255) / 256, 256>>>(knn);
    k_preph<<<128, 256>>>(lin_w);
    k_prepw<<<16, 256>>>(fw1, fw2);
    k_prepf<<<(NP * 32 + 255) / 256, 256>>>(feats);

    // stage 1
    k_fmma<<<NBLK, 256>>>(d_fh, d_w1h, fb1, d_g1, F1_OFF);
    k_w1<<<2048, 256>>>(xyz, cov, feats, knn, ww1, wb1);
    k_fin<<<1, 64>>>(F1_OFF, fg1, fbe1, 64, invNK);
    k_fin<<<1, 64>>>(W1_OFF, wg1, wbe1, 8, invNK);

    // stage 2
    k_mid<<<(NP * 32 + 255) / 256, 256>>>();
    k_fmma<<<NBLK, 256>>>(d_g1h, d_w2h, fb2, d_g2, F2_OFF);
    k_w2<<<2048, 256>>>(ww2, wb2);
    k_fin<<<1, 64>>>(F2_OFF, fg2, fbe2, 64, invNK);
    k_fin<<<1, 64>>>(W2_OFF, wg2, wbe2, 8, invNK);

    // fpost + stage 3 (w path)
    k_post<<<(NP * 32 + 255) / 256, 256>>>();
    k_w3s<<<2048, 256>>>(ww3, wb3);
    k_fin<<<1, 64>>>(W3_OFF, wg3, wbe3, 16, invNK);

    // einsum (tensor cores) + GEMM + final BN
    k_newmma<<<NP / 8, 256>>>(knn, ww3, wb3);
    k_gemm<<<NBLK, 256, SMEM_G>>>(lin_b);
    k_zstats<<<512, 256>>>();
    k_fin<<<1, 64>>>(Z_OFF, bng, bnb, 64, invN);
    k_out<<<(NP * 64 + 255) / 256, 256>>>(out);
}

// round 7
// speedup vs baseline: 1.4277x; 1.0987x over previous
#include <cuda_runtime.h>
#include <cuda_fp16.h>

#define NP 100000
#define KN 16
#define NK (NP*KN)

// ---------------- device scratch ----------------
__device__ int      g_cnt[NP];
__device__ float    g_g1[NP*64];          // f-path layer1 pre-BN (fp32)
__device__ float    g_g2[NP*64];          // f-path layer2 pre-BN (fp32)
__device__ unsigned g_fh[NP*32];          // feats as half2 words, K-permuted
__device__ unsigned g_g1h[NP*32];         // relu(BN1(g1)) as half2 words, K-permuted
__device__ __align__(16) __half g_fph[NP*64];  // fpost = relu(BN2(g2)) fp16, linear
__device__ unsigned g_w1h[64*32];         // fw1 half2, K-permuted
__device__ unsigned g_w2h[64*32];         // fw2 half2, K-permuted
__device__ float    g_y1w[NK*8];
__device__ float    g_y2w[NK*8];
__device__ unsigned g_newh[NP*512];       // new_flat as half2 words, K-permuted
__device__ unsigned g_lwth[64*512];       // lin_w as half2 words, K-permuted
__device__ float    g_z[NP*64];
__device__ float    g_stats[448];
__device__ float    g_ss[448];

#define F1_OFF 0
#define W1_OFF 128
#define F2_OFF 144
#define W2_OFF 272
#define W3_OFF 288
#define Z_OFF  320

#define EPS_BN 1e-5f

// ---------------- init ----------------
__global__ void k_zero() {
    int i = blockIdx.x * 256 + threadIdx.x;
    if (i < NP)  g_cnt[i] = 0;
    if (i < 448) g_stats[i] = 0.f;
}

__global__ void k_cnt(const int* __restrict__ knn) {
    int i = blockIdx.x * 256 + threadIdx.x;
    if (i < NK) atomicAdd(&g_cnt[knn[i]], 1);
}

// ---------------- stats helper ----------------
template<int CH>
__device__ __forceinline__ void stats_reduce(float* ls, float* lss, int off) {
    const unsigned FULL = 0xffffffffu;
    #pragma unroll
    for (int c = 0; c < CH; c++) {
        #pragma unroll
        for (int o = 16; o; o >>= 1) {
            ls[c]  += __shfl_down_sync(FULL, ls[c],  o);
            lss[c] += __shfl_down_sync(FULL, lss[c], o);
        }
    }
    __shared__ float sred[2 * 8 * CH];
    int wid = threadIdx.x >> 5, lane = threadIdx.x & 31;
    if (lane == 0) {
        #pragma unroll
        for (int c = 0; c < CH; c++) {
            sred[wid * CH + c]          = ls[c];
            sred[8 * CH + wid * CH + c] = lss[c];
        }
    }
    __syncthreads();
    if (threadIdx.x < CH) {
        float a = 0.f, b = 0.f;
        #pragma unroll
        for (int w = 0; w < 8; w++) {
            a += sred[w * CH + threadIdx.x];
            b += sred[8 * CH + w * CH + threadIdx.x];
        }
        atomicAdd(&g_stats[off + threadIdx.x], a);
        atomicAdd(&g_stats[off + CH + threadIdx.x], b);
    }
}

// ---------------- fp16 helpers ----------------
__device__ __forceinline__ unsigned packh2(float a, float b) {
    __half2 h = __floats2half2_rn(a, b);
    return *(unsigned*)&h;
}

__device__ __forceinline__ void mma_f16(float* c, unsigned a0, unsigned a1,
                                        unsigned a2, unsigned a3,
                                        unsigned b0, unsigned b1) {
    asm volatile("mma.sync.aligned.m16n8k16.row.col.f32.f16.f16.f32 "
                 "{%0,%1,%2,%3}, {%4,%5,%6,%7}, {%8,%9}, {%0,%1,%2,%3};"
                 : "+f"(c[0]), "+f"(c[1]), "+f"(c[2]), "+f"(c[3])
                 : "r"(a0), "r"(a1), "r"(a2), "r"(a3), "r"(b0), "r"(b1));
}

__device__ __forceinline__ void cp16(void* sptr, const void* gptr) {
    unsigned saddr = (unsigned)__cvta_generic_to_shared(sptr);
    asm volatile("cp.async.cg.shared.global [%0], [%1], 16;" :: "r"(saddr), "l"(gptr));
}

__device__ __forceinline__ unsigned smem_u32x(const void* p) {
    return (unsigned)__cvta_generic_to_shared(p);
}

__device__ __forceinline__ void ldsm_x4_trans(unsigned& r0, unsigned& r1,
                                              unsigned& r2, unsigned& r3, unsigned addr) {
    asm volatile("ldmatrix.sync.aligned.m8n8.x4.trans.shared.b16 {%0,%1,%2,%3}, [%4];"
                 : "=r"(r0), "=r"(r1), "=r"(r2), "=r"(r3) : "r"(addr));
}

__device__ __forceinline__ void ldsm_x2(unsigned& r0, unsigned& r1, unsigned addr) {
    asm volatile("ldmatrix.sync.aligned.m8n8.x2.shared.b16 {%0,%1}, [%2];"
                 : "=r"(r0), "=r"(r1) : "r"(addr));
}

__device__ __forceinline__ int wperm(int j) {   // word pos within 8-word k-group
    return ((j & 3) << 1) | (j >> 2);
}

// ---------------- preps: fp32 -> half2 words, K-permuted ----------------
__global__ void k_prepf(const float* __restrict__ src) {   // feats -> g_fh
    int i = blockIdx.x * 256 + threadIdx.x;
    if (i < NP * 32) {
        int row = i >> 5, W = i & 31;
        unsigned v = packh2(src[row * 64 + 2 * W], src[row * 64 + 2 * W + 1]);
        g_fh[row * 32 + (W & ~7) + wperm(W & 7)] = v;
    }
}

__global__ void k_prepw(const float* __restrict__ w1, const float* __restrict__ w2) {
    int i = blockIdx.x * 256 + threadIdx.x;
    if (i < 2 * 64 * 32) {
        const float* src = (i < 64 * 32) ? w1 : w2;
        unsigned* dst = (i < 64 * 32) ? g_w1h : g_w2h;
        int r = i & (64 * 32 - 1);
        int row = r >> 5, W = r & 31;
        unsigned v = packh2(src[row * 64 + 2 * W], src[row * 64 + 2 * W + 1]);
        dst[row * 32 + (W & ~7) + wperm(W & 7)] = v;
    }
}

__global__ void k_preph(const float* __restrict__ lw) {   // lin_w -> g_lwth
    int i = blockIdx.x * 256 + threadIdx.x;
    if (i < 64 * 512) {
        int row = i >> 9, W = i & 511;
        unsigned v = packh2(lw[row * 1024 + 2 * W], lw[row * 1024 + 2 * W + 1]);
        g_lwth[row * 512 + (W & ~7) + wperm(W & 7)] = v;
    }
}

// ---------------- mid: g1h = half(relu(BN1(g_g1))), K-permuted ----------------
__global__ void k_mid() {
    int i = blockIdx.x * 256 + threadIdx.x;
    if (i < NP * 32) {
        int row = i >> 5, W = i & 31;
        int c = 2 * W;
        float y0 = g_g1[row * 64 + c], y1 = g_g1[row * 64 + c + 1];
        y0 = fmaxf(g_ss[F1_OFF + c] * y0 + g_ss[F1_OFF + 64 + c], 0.f);
        y1 = fmaxf(g_ss[F1_OFF + c + 1] * y1 + g_ss[F1_OFF + 64 + c + 1], 0.f);
        g_g1h[row * 32 + (W & ~7) + wperm(W & 7)] = packh2(y0, y1);
    }
}

// ---------------- f-path conv via fp16 mma ----------------
#define FP 36
#define FA (128*FP)
#define FB (64*FP)

__global__ __launch_bounds__(256) void k_fmma(const unsigned* __restrict__ inH,
                                              const unsigned* __restrict__ wH,
                                              const float* __restrict__ B,
                                              float* __restrict__ dst,
                                              int statoff) {
    __shared__ unsigned As[FA];
    __shared__ unsigned Bs[FB];
    __shared__ float sred[128];
    int t = threadIdx.x;
    int rbase = blockIdx.x * 128;
    int lane = t & 31, grp = lane >> 2, qid = lane & 3;
    int m0 = (t >> 5) * 16;

    if (rbase + 128 > NP) {
        for (int i = t; i < FA; i += 256) As[i] = 0u;
        __syncthreads();
    }
    if (t < 128) sred[t] = 0.f;

    #pragma unroll
    for (int r4 = 0; r4 < 4; r4++) {
        int seg = t + r4 * 256;
        int row = seg >> 3, w16 = seg & 7;
        if (rbase + row < NP)
            cp16(As + row * FP + w16 * 4, inH + (size_t)(rbase + row) * 32 + w16 * 4);
    }
    #pragma unroll
    for (int r2 = 0; r2 < 2; r2++) {
        int seg = t + r2 * 256;
        int row = seg >> 3, w16 = seg & 7;
        cp16(Bs + row * FP + w16 * 4, wH + row * 32 + w16 * 4);
    }
    asm volatile("cp.async.commit_group;");
    asm volatile("cp.async.wait_group 0;");
    __syncthreads();

    float cf[8][4];
    #pragma unroll
    for (int nt = 0; nt < 8; nt++)
        #pragma unroll
        for (int j = 0; j < 4; j++) cf[nt][j] = 0.f;

    #pragma unroll
    for (int ks = 0; ks < 4; ks++) {
        uint2 aLo = *(uint2*)&As[(m0 + grp) * FP + ks * 8 + qid * 2];
        uint2 aHi = *(uint2*)&As[(m0 + grp + 8) * FP + ks * 8 + qid * 2];
        #pragma unroll
        for (int nt = 0; nt < 8; nt++) {
            uint2 b = *(uint2*)&Bs[(nt * 8 + grp) * FP + ks * 8 + qid * 2];
            mma_f16(cf[nt], aLo.x, aHi.x, aLo.y, aHi.y, b.x, b.y);
        }
    }

    int r0 = rbase + m0 + grp, r1 = r0 + 8;
    float w0 = (r0 < NP) ? (float)g_cnt[r0] : 0.f;
    float w1v = (r1 < NP) ? (float)g_cnt[r1] : 0.f;
    #pragma unroll
    for (int nt = 0; nt < 8; nt++) {
        int c0 = nt * 8 + 2 * qid;
        float b0v = __ldg(&B[c0]), b1v = __ldg(&B[c0 + 1]);
        float z0 = cf[nt][0] + b0v, z1 = cf[nt][1] + b1v;
        float z2 = cf[nt][2] + b0v, z3 = cf[nt][3] + b1v;
        if (r0 < NP) *(float2*)&dst[(size_t)r0 * 64 + c0] = make_float2(z0, z1);
        if (r1 < NP) *(float2*)&dst[(size_t)r1 * 64 + c0] = make_float2(z2, z3);
        atomicAdd(&sred[c0],     w0 * z0 + w1v * z2);
        atomicAdd(&sred[c0 + 1], w0 * z1 + w1v * z3);
        atomicAdd(&sred[64 + c0],     w0 * z0 * z0 + w1v * z2 * z2);
        atomicAdd(&sred[64 + c0 + 1], w0 * z1 * z1 + w1v * z3 * z3);
    }
    __syncthreads();
    if (t < 128) atomicAdd(&g_stats[statoff + t], sred[t]);
}

// ---------------- w-path layer 1 ----------------
__global__ __launch_bounds__(256, 3) void k_w1(const float* __restrict__ xyz,
                                               const float* __restrict__ cov,
                                               const float* __restrict__ feats,
                                               const int* __restrict__ knn,
                                               const float* __restrict__ ww1,
                                               const float* __restrict__ wb1) {
    __shared__ float wsm[112];
    __shared__ float bsm[8];
    int t = threadIdx.x;
    if (t < 112) wsm[t] = ww1[t];
    if (t < 8)   bsm[t] = wb1[t];
    __syncthreads();
    float ls[8], lss[8];
    #pragma unroll
    for (int o = 0; o < 8; o++) { ls[o] = 0.f; lss[o] = 0.f; }
    for (int i = blockIdx.x * 256 + t; i < NK; i += gridDim.x * 256) {
        int n = i >> 4;
        int j  = knn[i];
        int j0 = knn[n << 4];
        float lx = xyz[j * 3 + 0] - xyz[j0 * 3 + 0];
        float ly = xyz[j * 3 + 1] - xyz[j0 * 3 + 1];
        float lz = xyz[j * 3 + 2] - xyz[j0 * 3 + 2];
        float nax = feats[j * 64 + 3],  nay = feats[j * 64 + 4],  naz = feats[j * 64 + 5];
        float nmx = feats[j0 * 64 + 3], nmy = feats[j0 * 64 + 4], nmz = feats[j0 * 64 + 5];
        float rn = sqrtf(lx * lx + ly * ly + lz * lz);
        float inv = 1.f / fmaxf(rn, 1e-12f);
        float rx = lx * inv, ry = ly * inv, rz = lz * inv;
        float dot = nmx * rx + nmy * ry + nmz * rz;
        float vx = nmx - dot * rx, vy = nmy - dot * ry, vz = nmz - dot * rz;
        float vi = 1.f / fmaxf(sqrtf(vx * vx + vy * vy + vz * vz), 1e-12f);
        vx *= vi; vy *= vi; vz *= vi;
        float wx = ry * vz - rz * vy;
        float wy = rz * vx - rx * vz;
        float wz = rx * vy - ry * vx;
        float wi = 1.f / fmaxf(sqrtf(wx * wx + wy * wy + wz * wz), 1e-12f);
        wx *= wi; wy *= wi; wz *= wi;
        float t1 = nax * nmx + nay * nmy + naz * nmz;
        float t3 = rx * nax + ry * nay + rz * naz;
        float t4 = lx * nmx + ly * nmy + lz * nmz;
        float t6 = nax * vx + nay * vy + naz * vz;
        float t7 = nax * wx + nay * wy + naz * wz;
        float cx = nay * nmz - naz * nmy;
        float cy = naz * nmx - nax * nmz;
        float cz = nax * nmy - nay * nmx;
        float t8 = lx * cx + ly * cy + lz * cz;
        const float* cg = &cov[j * 9];
        float s1 = lx * (cg[0] * lx + cg[1] * ly + cg[2] * lz)
                 + ly * (cg[3] * lx + cg[4] * ly + cg[5] * lz)
                 + lz * (cg[6] * lx + cg[7] * ly + cg[8] * lz);
        const float* c0 = &cov[j0 * 9];
        float s2 = lx * (c0[0] * lx + c0[1] * ly + c0[2] * lz)
                 + ly * (c0[3] * lx + c0[4] * ly + c0[5] * lz)
                 + lz * (c0[6] * lx + c0[7] * ly + c0[8] * lz);
        float win[14] = {lx, ly, lz, t1, dot, t3, t4, t3, t6, t7, t8, rn, s1, s2};
        float ya[8];
        #pragma unroll
        for (int o = 0; o < 8; o++) {
            float y = bsm[o];
            #pragma unroll
            for (int c = 0; c < 14; c++) y += wsm[o * 14 + c] * win[c];
            ya[o] = y;
            ls[o] += y; lss[o] += y * y;
        }
        float4* dst = (float4*)&g_y1w[i * 8];
        dst[0] = make_float4(ya[0], ya[1], ya[2], ya[3]);
        dst[1] = make_float4(ya[4], ya[5], ya[6], ya[7]);
    }
    stats_reduce<8>(ls, lss, W1_OFF);
}

// ---------------- w-path layer 2 ----------------
__global__ __launch_bounds__(256) void k_w2(const float* __restrict__ ww2,
                                            const float* __restrict__ wb2) {
    __shared__ float wsm[64], bsm[8], ssc[8], ssh[8];
    int t = threadIdx.x;
    if (t < 64) wsm[t] = ww2[t];
    if (t < 8) { bsm[t] = wb2[t]; ssc[t] = g_ss[W1_OFF + t]; ssh[t] = g_ss[W1_OFF + 8 + t]; }
    __syncthreads();
    float ls[8], lss[8];
    #pragma unroll
    for (int o = 0; o < 8; o++) { ls[o] = 0.f; lss[o] = 0.f; }
    for (int i = blockIdx.x * 256 + t; i < NK; i += gridDim.x * 256) {
        float a[8];
        float4 a0 = *(const float4*)&g_y1w[i * 8];
        float4 a1 = *(const float4*)&g_y1w[i * 8 + 4];
        a[0] = a0.x; a[1] = a0.y; a[2] = a0.z; a[3] = a0.w;
        a[4] = a1.x; a[5] = a1.y; a[6] = a1.z; a[7] = a1.w;
        #pragma unroll
        for (int c = 0; c < 8; c++) a[c] = fmaxf(ssc[c] * a[c] + ssh[c], 0.f);
        float ya[8];
        #pragma unroll
        for (int o = 0; o < 8; o++) {
            float y = bsm[o];
            #pragma unroll
            for (int c = 0; c < 8; c++) y += wsm[o * 8 + c] * a[c];
            ya[o] = y;
            ls[o] += y; lss[o] += y * y;
        }
        float4* dst = (float4*)&g_y2w[i * 8];
        dst[0] = make_float4(ya[0], ya[1], ya[2], ya[3]);
        dst[1] = make_float4(ya[4], ya[5], ya[6], ya[7]);
    }
    stats_reduce<8>(ls, lss, W2_OFF);
}

// ---------------- w-path layer 3: stats only ----------------
__global__ __launch_bounds__(256) void k_w3s(const float* __restrict__ ww3,
                                             const float* __restrict__ wb3) {
    __shared__ float wsm[128], bsm[16], ssc[8], ssh[8];
    int t = threadIdx.x;
    if (t < 128) wsm[t] = ww3[t];
    if (t < 16)  bsm[t] = wb3[t];
    if (t < 8) { ssc[t] = g_ss[W2_OFF + t]; ssh[t] = g_ss[W2_OFF + 8 + t]; }
    __syncthreads();
    float ls[16], lss[16];
    #pragma unroll
    for (int o = 0; o < 16; o++) { ls[o] = 0.f; lss[o] = 0.f; }
    for (int i = blockIdx.x * 256 + t; i < NK; i += gridDim.x * 256) {
        float a[8];
        float4 a0 = *(const float4*)&g_y2w[i * 8];
        float4 a1 = *(const float4*)&g_y2w[i * 8 + 4];
        a[0] = a0.x; a[1] = a0.y; a[2] = a0.z; a[3] = a0.w;
        a[4] = a1.x; a[5] = a1.y; a[6] = a1.z; a[7] = a1.w;
        #pragma unroll
        for (int c = 0; c < 8; c++) a[c] = fmaxf(ssc[c] * a[c] + ssh[c], 0.f);
        #pragma unroll
        for (int o = 0; o < 16; o++) {
            float y = bsm[o];
            #pragma unroll
            for (int c = 0; c < 8; c++) y += wsm[o * 8 + c] * a[c];
            ls[o] += y; lss[o] += y * y;
        }
    }
    stats_reduce<16>(ls, lss, W3_OFF);
}

// ---------------- finalize BN ----------------
__global__ void k_fin(int off, const float* __restrict__ gamma,
                      const float* __restrict__ beta, int nch, float invc) {
    int c = threadIdx.x;
    if (c < nch) {
        float m = g_stats[off + c] * invc;
        float v = g_stats[off + nch + c] * invc - m * m;
        float s = gamma[c] / sqrtf(v + EPS_BN);
        g_ss[off + c] = s;
        g_ss[off + nch + c] = beta[c] - m * s;
    }
}

// ---------------- fpost = half(relu(BN2(g_g2))) ----------------
__global__ void k_post() {
    int i = blockIdx.x * 256 + threadIdx.x;
    if (i < NP * 32) {
        int c = (2 * i) & 63;
        float y0 = g_g2[2 * i],     y1 = g_g2[2 * i + 1];
        y0 = fmaxf(g_ss[F2_OFF + c] * y0 + g_ss[F2_OFF + 64 + c], 0.f);
        y1 = fmaxf(g_ss[F2_OFF + c + 1] * y1 + g_ss[F2_OFF + 64 + c + 1], 0.f);
        *(unsigned*)&g_fph[2 * i] = packh2(y0, y1);
    }
}

// ---------------- new = f @ w^T per point, tensor cores ----------------
__global__ __launch_bounds__(256) void k_newmma(const int* __restrict__ knn,
                                                const float* __restrict__ ww3,
                                                const float* __restrict__ wb3) {
    __shared__ __align__(16) __half st[8][16 * 72];   // [warp][k][h]
    __shared__ __align__(16) __half ws[8][16 * 24];   // [warp][m][k]
    __shared__ float sww3[128], swb3[16], sc3[16], sh3[16], sc2[8], sh2[8];
    int t = threadIdx.x, w = t >> 5, l = t & 31;
    if (t < 128) sww3[t] = ww3[t];
    if (t < 16) {
        swb3[t] = wb3[t];
        sc3[t] = g_ss[W3_OFF + t];
        sh3[t] = g_ss[W3_OFF + 16 + t];
    }
    if (t >= 16 && t < 24) {
        int c = t - 16;
        sc2[c] = g_ss[W2_OFF + c];
        sh2[c] = g_ss[W2_OFF + 8 + c];
    }
    __syncthreads();

    int n = blockIdx.x * 8 + w;
    int sjv = knn[n * 16 + (l & 15)];
    int jj = __shfl_sync(0xffffffffu, sjv, l >> 1);

    {
        const uint4* src = (const uint4*)(g_fph + (size_t)jj * 64 + (l & 1) * 32);
        uint4* dst = (uint4*)&st[w][(l >> 1) * 72 + (l & 1) * 32];
        dst[0] = src[0]; dst[1] = src[1]; dst[2] = src[2]; dst[3] = src[3];
    }

    if (l < 16) {
        int base = (n * 16 + l) * 8;
        float a[8];
        float4 a0 = *(const float4*)&g_y2w[base];
        float4 a1 = *(const float4*)&g_y2w[base + 4];
        a[0] = a0.x; a[1] = a0.y; a[2] = a0.z; a[3] = a0.w;
        a[4] = a1.x; a[5] = a1.y; a[6] = a1.z; a[7] = a1.w;
        #pragma unroll
        for (int c = 0; c < 8; c++) a[c] = fmaxf(sc2[c] * a[c] + sh2[c], 0.f);
        #pragma unroll
        for (int m = 0; m < 16; m++) {
            float y = swb3[m];
            #pragma unroll
            for (int c = 0; c < 8; c++) y += sww3[m * 8 + c] * a[c];
            ws[w][m * 24 + l] = __float2half(fmaxf(sc3[m] * y + sh3[m], 0.f));
        }
    }
    __syncwarp();

    unsigned bf[2][2];
    #pragma unroll
    for (int mg = 0; mg < 2; mg++) {
        int q = l & 15;
        unsigned addr = smem_u32x(&ws[w][(mg * 8 + (q & 7)) * 24 + (q >> 3) * 8]);
        ldsm_x2(bf[mg][0], bf[mg][1], addr);
    }

    float d[4][2][4] = {};
    int matid = l >> 3;
    int krow = (l & 7) + ((matid >> 1) << 3);
    int coff = (matid & 1) * 8;

    #pragma unroll
    for (int hg = 0; hg < 4; hg++) {
        unsigned a0, a1, a2, a3;
        unsigned addr = smem_u32x(&st[w][krow * 72 + hg * 16 + coff]);
        ldsm_x4_trans(a0, a1, a2, a3, addr);
        #pragma unroll
        for (int mg = 0; mg < 2; mg++)
            mma_f16(d[hg][mg], a0, a1, a2, a3, bf[mg][0], bf[mg][1]);
    }

    int g = l >> 2, tt = l & 3;
    unsigned* row = g_newh + (size_t)n * 512;
    #pragma unroll
    for (int hg = 0; hg < 4; hg++) {
        int h = hg * 16 + g;
        #pragma unroll
        for (int mg = 0; mg < 2; mg++) {
            int pos = wperm(mg * 4 + tt);
            row[h * 8 + pos]       = packh2(d[hg][mg][0], d[hg][mg][1]);
            row[(h + 8) * 8 + pos] = packh2(d[hg][mg][2], d[hg][mg][3]);
        }
    }
}

// ---------------- GEMM: z = new(NPx1024) @ lin_w^T(1024x64) ----------------
#define GP 36
#define GA (128*GP)
#define GB (64*GP)
#define SMEM_G ((2*GA + 2*GB)*4)

__global__ __launch_bounds__(256, 3) void k_gemm(const float* __restrict__ lb) {
    extern __shared__ unsigned sm[];
    unsigned* As[2] = { sm, sm + GA };
    unsigned* Bs[2] = { sm + 2 * GA, sm + 2 * GA + GB };
    int t = threadIdx.x;
    int rbase = blockIdx.x * 128;
    int lane = t & 31, grp = lane >> 2, qid = lane & 3;
    int m0 = (t >> 5) * 16;

    if (rbase + 128 > NP) {
        for (int i = t; i < 2 * GA; i += 256) sm[i] = 0u;
        __syncthreads();
    }

    float cf[8][4];
    #pragma unroll
    for (int nt = 0; nt < 8; nt++)
        #pragma unroll
        for (int j = 0; j < 4; j++) cf[nt][j] = 0.f;

    auto load = [&](int buf, int s) {
        int kc = s * 32;
        #pragma unroll
        for (int r4 = 0; r4 < 4; r4++) {
            int seg = t + r4 * 256;
            int row = seg >> 3, w16 = seg & 7;
            if (rbase + row < NP)
                cp16(As[buf] + row * GP + w16 * 4,
                     g_newh + (size_t)(rbase + row) * 512 + kc + w16 * 4);
        }
        #pragma unroll
        for (int r2 = 0; r2 < 2; r2++) {
            int seg = t + r2 * 256;
            int row = seg >> 3, w16 = seg & 7;
            cp16(Bs[buf] + row * GP + w16 * 4,
                 g_lwth + row * 512 + kc + w16 * 4);
        }
        asm volatile("cp.async.commit_group;");
    };

    load(0, 0);
    int cur = 0;
    for (int s = 0; s < 16; s++) {
        if (s < 15) {
            load(cur ^ 1, s + 1);
            asm volatile("cp.async.wait_group 1;");
        } else {
            asm volatile("cp.async.wait_group 0;");
        }
        __syncthreads();
        unsigned* A = As[cur];
        unsigned* B = Bs[cur];
        #pragma unroll
        for (int ks = 0; ks < 4; ks++) {
            uint2 aLo = *(uint2*)&A[(m0 + grp) * GP + ks * 8 + qid * 2];
            uint2 aHi = *(uint2*)&A[(m0 + grp + 8) * GP + ks * 8 + qid * 2];
            #pragma unroll
            for (int nt = 0; nt < 8; nt++) {
                uint2 b = *(uint2*)&B[(nt * 8 + grp) * GP + ks * 8 + qid * 2];
                mma_f16(cf[nt], aLo.x, aHi.x, aLo.y, aHi.y, b.x, b.y);
            }
        }
        __syncthreads();
        cur ^= 1;
    }

    int r0 = rbase + m0 + grp, r1 = r0 + 8;
    #pragma unroll
    for (int nt = 0; nt < 8; nt++) {
        int c0 = nt * 8 + 2 * qid;
        float b0v = __ldg(&lb[c0]), b1v = __ldg(&lb[c0 + 1]);
        if (r0 < NP) *(float2*)&g_z[r0 * 64 + c0] = make_float2(cf[nt][0] + b0v, cf[nt][1] + b1v);
        if (r1 < NP) *(float2*)&g_z[r1 * 64 + c0] = make_float2(cf[nt][2] + b0v, cf[nt][3] + b1v);
    }
}

// ---------------- stats over z ----------------
__global__ __launch_bounds__(256) void k_zstats() {
    __shared__ float sred[128];
    int t = threadIdx.x;
    if (t < 128) sred[t] = 0.f;
    __syncthreads();
    int cg = (t & 15) * 4;
    float s[4] = {0.f, 0.f, 0.f, 0.f}, ss[4] = {0.f, 0.f, 0.f, 0.f};
    for (int i = blockIdx.x * 256 + t; i < NP * 16; i += gridDim.x * 256) {
        float4 v = *(const float4*)&g_z[i * 4];
        s[0] += v.x; ss[0] += v.x * v.x;
        s[1] += v.y; ss[1] += v.y * v.y;
        s[2] += v.z; ss[2] += v.z * v.z;
        s[3] += v.w; ss[3] += v.w * v.w;
    }
    const unsigned FULL = 0xffffffffu;
    #pragma unroll
    for (int j = 0; j < 4; j++) {
        s[j]  += __shfl_down_sync(FULL, s[j], 16);
        ss[j] += __shfl_down_sync(FULL, ss[j], 16);
    }
    if ((t & 31) < 16) {
        #pragma unroll
        for (int j = 0; j < 4; j++) {
            atomicAdd(&sred[cg + j], s[j]);
            atomicAdd(&sred[64 + cg + j], ss[j]);
        }
    }
    __syncthreads();
    if (t < 128) atomicAdd(&g_stats[Z_OFF + t], sred[t]);
}

// ---------------- final BN + relu -> output ----------------
__global__ void k_out(float* __restrict__ out) {
    int i = blockIdx.x * 256 + threadIdx.x;
    if (i < NP * 64) {
        int c = i & 63;
        out[i] = fmaxf(g_ss[Z_OFF + c] * g_z[i] + g_ss[Z_OFF + 64 + c], 0.f);
    }
}

// ---------------- stream/event infra (created once at program init) ----------------
static cudaStream_t g_sF = nullptr;      // f-path fork stream
static cudaEvent_t  g_eFork = nullptr, g_eJoin = nullptr;
static int g_stream_init = ([]() {
    cudaStreamCreateWithFlags(&g_sF, cudaStreamNonBlocking);
    cudaEventCreateWithFlags(&g_eFork, cudaEventDisableTiming);
    cudaEventCreateWithFlags(&g_eJoin, cudaEventDisableTiming);
    return 0;
})();

// ---------------- launch ----------------
extern "C" void kernel_launch(void* const* d_in, const int* in_sizes, int n_in,
                              void* d_out, int out_size) {
    const float* xyz   = (const float*)d_in[0];
    const float* cov   = (const float*)d_in[1];
    const float* feats = (const float*)d_in[2];
    const int*   knn   = (const int*)  d_in[3];
    const float* fw1 = (const float*)d_in[4];
    const float* fb1 = (const float*)d_in[5];
    const float* fg1 = (const float*)d_in[6];
    const float* fbe1 = (const float*)d_in[7];
    const float* fw2 = (const float*)d_in[8];
    const float* fb2 = (const float*)d_in[9];
    const float* fg2 = (const float*)d_in[10];
    const float* fbe2 = (const float*)d_in[11];
    const float* ww1 = (const float*)d_in[12];
    const float* wb1 = (const float*)d_in[13];
    const float* wg1 = (const float*)d_in[14];
    const float* wbe1 = (const float*)d_in[15];
    const float* ww2 = (const float*)d_in[16];
    const float* wb2 = (const float*)d_in[17];
    const float* wg2 = (const float*)d_in[18];
    const float* wbe2 = (const float*)d_in[19];
    const float* ww3 = (const float*)d_in[20];
    const float* wb3 = (const float*)d_in[21];
    const float* wg3 = (const float*)d_in[22];
    const float* wbe3 = (const float*)d_in[23];
    const float* lin_w = (const float*)d_in[24];
    const float* lin_b = (const float*)d_in[25];
    const float* bng = (const float*)d_in[26];
    const float* bnb = (const float*)d_in[27];
    float* out = (float*)d_out;

    const float invNK = 1.f / (float)NK;
    const float invN  = 1.f / (float)NP;
    const int NBLK = (NP + 127) / 128;

    float* d_g1; cudaGetSymbolAddress((void**)&d_g1, g_g1);
    float* d_g2; cudaGetSymbolAddress((void**)&d_g2, g_g2);
    unsigned* d_fh;  cudaGetSymbolAddress((void**)&d_fh,  g_fh);
    unsigned* d_g1h; cudaGetSymbolAddress((void**)&d_g1h, g_g1h);
    unsigned* d_w1h; cudaGetSymbolAddress((void**)&d_w1h, g_w1h);
    unsigned* d_w2h; cudaGetSymbolAddress((void**)&d_w2h, g_w2h);

    cudaFuncSetAttribute(k_gemm, cudaFuncAttributeMaxDynamicSharedMemorySize, SMEM_G);

    cudaStream_t sF = g_sF;

    // ---- common init on main stream ----
    k_zero<<<(NP + 255) / 256, 256>>>();
    k_cnt<<<(NK + 255) / 256, 256>>>(knn);

    // ---- fork: f-path + preps on sF ----
    cudaEventRecord(g_eFork, 0);
    cudaStreamWaitEvent(sF, g_eFork, 0);

    k_prepf<<<(NP * 32 + 255) / 256, 256, 0, sF>>>(feats);
    k_prepw<<<16, 256, 0, sF>>>(fw1, fw2);
    k_preph<<<128, 256, 0, sF>>>(lin_w);
    k_fmma<<<NBLK, 256, 0, sF>>>(d_fh, d_w1h, fb1, d_g1, F1_OFF);
    k_fin<<<1, 64, 0, sF>>>(F1_OFF, fg1, fbe1, 64, invNK);
    k_mid<<<(NP * 32 + 255) / 256, 256, 0, sF>>>();
    k_fmma<<<NBLK, 256, 0, sF>>>(d_g1h, d_w2h, fb2, d_g2, F2_OFF);
    k_fin<<<1, 64, 0, sF>>>(F2_OFF, fg2, fbe2, 64, invNK);
    k_post<<<(NP * 32 + 255) / 256, 256, 0, sF>>>();
    cudaEventRecord(g_eJoin, sF);

    // ---- w-path on main stream (concurrent with sF) ----
    k_w1<<<2048, 256>>>(xyz, cov, feats, knn, ww1, wb1);
    k_fin<<<1, 64>>>(W1_OFF, wg1, wbe1, 8, invNK);
    k_w2<<<2048, 256>>>(ww2, wb2);
    k_fin<<<1, 64>>>(W2_OFF, wg2, wbe2, 8, invNK);
    k_w3s<<<2048, 256>>>(ww3, wb3);
    k_fin<<<1, 64>>>(W3_OFF, wg3, wbe3, 16, invNK);

    // ---- join ----
    cudaStreamWaitEvent(0, g_eJoin, 0);

    // einsum (tensor cores) + GEMM + final BN
    k_newmma<<<NP / 8, 256>>>(knn, ww3, wb3);
    k_gemm<<<NBLK, 256, SMEM_G>>>(lin_b);
    k_zstats<<<512, 256>>>();
    k_fin<<<1, 64>>>(Z_OFF, bng, bnb, 64, invN);
    k_out<<<(NP * 64 + 255) / 256, 256>>>(out);
}